// round 11
// baseline (speedup 1.0000x reference)
#include <cuda_runtime.h>

#define BN 1024
#define CN 128
#define DN 16
#define SN 4
#define K3N 23
#define K2N 5
#define K1N 2
#define ON 4

// Stream layout per (e,c), consumed in exactly this order:
//   for i in 0..15:  [S1: 4 floats]
//     for j in i..15:  [S2: 4 floats]
//       for h in (j>>1)..7:  [8 floats: (o0l0,o0l1,o1l0,o1l1,o2l0,o2l1,o3l0,o3l1)]
// total floats = 16*4 + 136*4 + 444*8 = 4160
#define STREAMF 4160
#define NSLOTS  596   // 16 S1 + 136 S2 + 444 h-slots

#define FCH 8         // final channel chunks
#define FCW 16        // channels per chunk

// ---------------- static device scratch ----------------
__device__ float g_stream[(size_t)SN * CN * STREAMF];   // 8.5 MB
__device__ float g_y[(size_t)BN * CN * ON];
__device__ float g_part[(size_t)FCH * BN * 512];        // 16.8 MB partials
__device__ int   g_bucket[SN * BN];
__device__ int   g_cnt[SN];
__device__ int   g_sched[16];
__device__ int   g_nsched;

// ---------------- kernel 1: bucket nodes by species + 256-node chunk schedule ----------------
__global__ void bucket_kernel(const int* __restrict__ sp) {
    __shared__ int scnt[SN];
    int t = threadIdx.x;                 // exactly BN threads
    if (t < SN) scnt[t] = 0;
    __syncthreads();
    int e = sp[t];
    int pos = atomicAdd(&scnt[e], 1);
    g_bucket[e * BN + pos] = t;
    __syncthreads();
    if (t < SN) g_cnt[t] = scnt[t];
    if (t == 0) {
        int n = 0;
        for (int e2 = 0; e2 < SN; e2++)
            for (int s2 = 0; s2 < scnt[e2]; s2 += 256)
                g_sched[n++] = (e2 << 16) | s2;
        g_nsched = n;
    }
}

// ---------------- symmetrized-u helpers ----------------
__device__ __forceinline__ float u3val(int o, int i, int j, int l, int k,
                                       const float* __restrict__ u3_0,
                                       const float* __restrict__ u3_1) {
    return (o == 0) ? u3_0[((i * 16 + j) * 16 + l) * K3N + k]
                    : u3_1[((((o - 1) * 16 + i) * 16 + j) * 16 + l) * K3N + k];
}
// orbit sum over distinct permutations of sorted triple a<=b<=g
__device__ __forceinline__ float orbit3(int o, int a, int b, int g, int k,
                                        const float* __restrict__ A,
                                        const float* __restrict__ B) {
    if (a == b && b == g) return u3val(o, a, a, a, k, A, B);
    if (a == b) return u3val(o, a, a, g, k, A, B) + u3val(o, a, g, a, k, A, B) + u3val(o, g, a, a, k, A, B);
    if (b == g) return u3val(o, a, b, b, k, A, B) + u3val(o, b, a, b, k, A, B) + u3val(o, b, b, a, k, A, B);
    return u3val(o, a, b, g, k, A, B) + u3val(o, a, g, b, k, A, B) + u3val(o, b, a, g, k, A, B)
         + u3val(o, b, g, a, k, A, B) + u3val(o, g, a, b, k, A, B) + u3val(o, g, b, a, k, A, B);
}
__device__ __forceinline__ float u2val(int o, int i, int j, int k,
                                       const float* __restrict__ u2_0,
                                       const float* __restrict__ u2_1) {
    return (o == 0) ? u2_0[(i * 16 + j) * K2N + k]
                    : u2_1[(((o - 1) * 16 + i) * 16 + j) * K2N + k];
}

// ---------------- kernel 2: build coefficient stream ----------------
// grid = 4 species * 596 slots; 128 threads = channel c.
__global__ void sbuild_kernel(const float* __restrict__ u3_0, const float* __restrict__ u3_1,
                              const float* __restrict__ u2_0, const float* __restrict__ u2_1,
                              const float* __restrict__ u1_0, const float* __restrict__ u1_1,
                              const float* __restrict__ w3,   const float* __restrict__ w2,
                              const float* __restrict__ w1) {
    int e = blockIdx.x / NSLOTS;
    int slot = blockIdx.x % NSLOTS;
    int c = threadIdx.x;

    // locate this slot in the canonical stream order (thread 0 only, broadcast)
    __shared__ int sinfo[5];
    if (threadIdx.x == 0) {
        int s = slot, type = -1, I = 0, J = 0, H = 0, mypos = 0, pos = 0;
        for (int i = 0; i < 16 && type < 0; i++) {
            if (s == 0) { type = 0; I = i; mypos = pos; break; }
            s--; pos += 4;
            for (int j = i; j < 16; j++) {
                if (s == 0) { type = 1; I = i; J = j; mypos = pos; break; }
                s--; pos += 4;
                int nh = 8 - (j >> 1);
                if (s < nh) { type = 2; I = i; J = j; H = (j >> 1) + s; mypos = pos + s * 8; break; }
                s -= nh; pos += nh * 8;
            }
        }
        sinfo[0] = type; sinfo[1] = I; sinfo[2] = J; sinfo[3] = H; sinfo[4] = mypos;
    }
    __syncthreads();
    int type = sinfo[0], I = sinfo[1], J = sinfo[2], H = sinfo[3], mypos = sinfo[4];
    size_t base = (size_t)(e * CN + c) * STREAMF + mypos;

    if (type == 0) {            // S1: uw1[o,I]
#pragma unroll
        for (int o = 0; o < 4; o++) {
            int tt = (o > 0);
            float acc = 0.f;
#pragma unroll
            for (int k = 0; k < K1N; k++) {
                float uu = (o == 0) ? u1_0[I * K1N + k] : u1_1[((o - 1) * 16 + I) * K1N + k];
                acc = fmaf(uu, w1[((tt * SN + e) * K1N + k) * CN + c], acc);
            }
            g_stream[base + o] = acc;
        }
    } else if (type == 1) {     // S2: orbit-symmetrized uw2 for pair (I<=J)
#pragma unroll
        for (int o = 0; o < 4; o++) {
            int tt = (o > 0);
            float acc = 0.f;
#pragma unroll
            for (int k = 0; k < K2N; k++) {
                float uu = u2val(o, I, J, k, u2_0, u2_1);
                if (I < J) uu += u2val(o, J, I, k, u2_0, u2_1);
                acc = fmaf(uu, w2[((tt * SN + e) * K2N + k) * CN + c], acc);
            }
            g_stream[base + o] = acc;
        }
    } else {                    // h-slot: 8 values (4 o x 2 l), orbit-symmetrized uw3
        __shared__ float us[K3N][8];
        for (int v = threadIdx.x; v < K3N * 8; v += 128) {
            int k = v >> 3, q = v & 7;
            int o = q >> 1, dl = q & 1, l = 2 * H + dl;
            float val = 0.f;
            if (l >= J) val = orbit3(o, I, J, l, k, u3_0, u3_1);
            us[k][q] = val;
        }
        __syncthreads();
        float w3r0[K3N], w3r1[K3N];
#pragma unroll
        for (int k = 0; k < K3N; k++) {
            w3r0[k] = w3[((0 * SN + e) * K3N + k) * CN + c];
            w3r1[k] = w3[((1 * SN + e) * K3N + k) * CN + c];
        }
        float acc[8] = {0, 0, 0, 0, 0, 0, 0, 0};
#pragma unroll
        for (int k = 0; k < K3N; k++) {
            float4 a = *(const float4*)&us[k][0];
            float4 b = *(const float4*)&us[k][4];
            acc[0] = fmaf(a.x, w3r0[k], acc[0]);
            acc[1] = fmaf(a.y, w3r0[k], acc[1]);
            acc[2] = fmaf(a.z, w3r1[k], acc[2]);
            acc[3] = fmaf(a.w, w3r1[k], acc[3]);
            acc[4] = fmaf(b.x, w3r1[k], acc[4]);
            acc[5] = fmaf(b.y, w3r1[k], acc[5]);
            acc[6] = fmaf(b.z, w3r1[k], acc[6]);
            acc[7] = fmaf(b.w, w3r1[k], acc[7]);
        }
#pragma unroll
        for (int q = 0; q < 8; q++) g_stream[base + q] = acc[q];
    }
}

// ---------------- kernel 3: main contraction, 2 nodes per thread ----------------
// Block = (c, 256-node chunk of one species); thread n handles nodes n and n+128.
// Every stream LDS feeds BOTH nodes' math: ~3700 issues/node vs 4600 at 1 node/thread.
__global__ void __launch_bounds__(128) main_kernel(const float* __restrict__ x) {
    __shared__ float4 st4[STREAMF / 4];
    int bx = blockIdx.x;
    int c = bx & 127;
    int chunk = bx >> 7;
    if (chunk >= g_nsched) return;
    int si = g_sched[chunk];
    int e = si >> 16, start = si & 0xffff;

    // stage this (e,c) coefficient stream into smem (coalesced)
    const float4* src = (const float4*)(g_stream + (size_t)(e * CN + c) * STREAMF);
    for (int p = threadIdx.x; p < STREAMF / 4; p += 128) st4[p] = src[p];

    int cnt = g_cnt[e];
    int idx0 = start + threadIdx.x;
    int idx1 = start + 128 + threadIdx.x;
    bool act0 = idx0 < cnt, act1 = idx1 < cnt;
    int b0 = act0 ? g_bucket[e * BN + idx0] : 0;
    int b1 = act1 ? g_bucket[e * BN + idx1] : 0;

    float xa[16], xb[16];
    {
        float4 z = make_float4(0.f, 0.f, 0.f, 0.f);
        float4 r0[4] = {z, z, z, z}, r1[4] = {z, z, z, z};
        if (act0) {
            const float4* xp = (const float4*)(x + ((size_t)b0 * CN + c) * 16);
            r0[0] = xp[0]; r0[1] = xp[1]; r0[2] = xp[2]; r0[3] = xp[3];
        }
        if (act1) {
            const float4* xp = (const float4*)(x + ((size_t)b1 * CN + c) * 16);
            r1[0] = xp[0]; r1[1] = xp[1]; r1[2] = xp[2]; r1[3] = xp[3];
        }
#pragma unroll
        for (int q = 0; q < 4; q++) {
            *(float4*)&xa[q * 4] = r0[q];
            *(float4*)&xb[q * 4] = r1[q];
        }
    }
    unsigned long long Xa[8], Xb[8];
#pragma unroll
    for (int h = 0; h < 8; h++) {
        asm("mov.b64 %0, {%1, %2};" : "=l"(Xa[h]) : "f"(xa[2 * h]), "f"(xa[2 * h + 1]));
        asm("mov.b64 %0, {%1, %2};" : "=l"(Xb[h]) : "f"(xb[2 * h]), "f"(xb[2 * h + 1]));
    }

    __syncthreads();
    const float* sp = (const float*)st4;

    unsigned long long acc3a[4] = {0ull, 0ull, 0ull, 0ull};
    unsigned long long acc3b[4] = {0ull, 0ull, 0ull, 0ull};
    float accsa[4] = {0.f, 0.f, 0.f, 0.f};
    float accsb[4] = {0.f, 0.f, 0.f, 0.f};

#pragma unroll
    for (int i = 0; i < 16; i++) {
        float4 s1 = *(const float4*)sp; sp += 4;
        accsa[0] = fmaf(s1.x, xa[i], accsa[0]);
        accsa[1] = fmaf(s1.y, xa[i], accsa[1]);
        accsa[2] = fmaf(s1.z, xa[i], accsa[2]);
        accsa[3] = fmaf(s1.w, xa[i], accsa[3]);
        accsb[0] = fmaf(s1.x, xb[i], accsb[0]);
        accsb[1] = fmaf(s1.y, xb[i], accsb[1]);
        accsb[2] = fmaf(s1.z, xb[i], accsb[2]);
        accsb[3] = fmaf(s1.w, xb[i], accsb[3]);
#pragma unroll
        for (int j = i; j < 16; j++) {
            float pa = xa[i] * xa[j];
            float pb = xb[i] * xb[j];
            float4 s2 = *(const float4*)sp; sp += 4;
            accsa[0] = fmaf(s2.x, pa, accsa[0]);
            accsa[1] = fmaf(s2.y, pa, accsa[1]);
            accsa[2] = fmaf(s2.z, pa, accsa[2]);
            accsa[3] = fmaf(s2.w, pa, accsa[3]);
            accsb[0] = fmaf(s2.x, pb, accsb[0]);
            accsb[1] = fmaf(s2.y, pb, accsb[1]);
            accsb[2] = fmaf(s2.z, pb, accsb[2]);
            accsb[3] = fmaf(s2.w, pb, accsb[3]);
            unsigned long long pa2, pb2;
            asm("mov.b64 %0, {%1, %1};" : "=l"(pa2) : "f"(pa));
            asm("mov.b64 %0, {%1, %1};" : "=l"(pb2) : "f"(pb));
#pragma unroll
            for (int h = (j >> 1); h < 8; h++) {
                unsigned long long ma, mb;
                asm("mul.rn.f32x2 %0, %1, %2;" : "=l"(ma) : "l"(pa2), "l"(Xa[h]));
                asm("mul.rn.f32x2 %0, %1, %2;" : "=l"(mb) : "l"(pb2), "l"(Xb[h]));
                ulonglong2 qa = *(const ulonglong2*)sp;
                ulonglong2 qb = *(const ulonglong2*)(sp + 4);
                sp += 8;
                asm("fma.rn.f32x2 %0, %1, %2, %0;" : "+l"(acc3a[0]) : "l"(qa.x), "l"(ma));
                asm("fma.rn.f32x2 %0, %1, %2, %0;" : "+l"(acc3a[1]) : "l"(qa.y), "l"(ma));
                asm("fma.rn.f32x2 %0, %1, %2, %0;" : "+l"(acc3a[2]) : "l"(qb.x), "l"(ma));
                asm("fma.rn.f32x2 %0, %1, %2, %0;" : "+l"(acc3a[3]) : "l"(qb.y), "l"(ma));
                asm("fma.rn.f32x2 %0, %1, %2, %0;" : "+l"(acc3b[0]) : "l"(qa.x), "l"(mb));
                asm("fma.rn.f32x2 %0, %1, %2, %0;" : "+l"(acc3b[1]) : "l"(qa.y), "l"(mb));
                asm("fma.rn.f32x2 %0, %1, %2, %0;" : "+l"(acc3b[2]) : "l"(qb.x), "l"(mb));
                asm("fma.rn.f32x2 %0, %1, %2, %0;" : "+l"(acc3b[3]) : "l"(qb.y), "l"(mb));
            }
        }
    }

    if (act0) {
        float out[4];
#pragma unroll
        for (int o = 0; o < 4; o++) {
            float lo, hi;
            asm("mov.b64 {%0, %1}, %2;" : "=f"(lo), "=f"(hi) : "l"(acc3a[o]));
            out[o] = accsa[o] + lo + hi;
        }
        *(float4*)(g_y + ((size_t)b0 * CN + c) * ON) = *(float4*)out;
    }
    if (act1) {
        float out[4];
#pragma unroll
        for (int o = 0; o < 4; o++) {
            float lo, hi;
            asm("mov.b64 {%0, %1}, %2;" : "=f"(lo), "=f"(hi) : "l"(acc3b[o]));
            out[o] = accsb[o] + lo + hi;
        }
        *(float4*)(g_y + ((size_t)b1 * CN + c) * ON) = *(float4*)out;
    }
}

// ---------------- kernel 4a: equivariant linear, 8-way c-split partials ----------------
// grid = 1024 = (128 node-groups x 8 channel-chunks); block = 256 threads.
// w L2 traffic invariant under chunk count (~33 MB); 8x grid -> issue-bound.
#define NBF 8
__global__ void __launch_bounds__(256) final_part(const float* __restrict__ w_lin) {
    __shared__ float ysm[FCW][4][NBF];   // [ci][oo][nn], 2 KB
    int nodeblk = blockIdx.x >> 3;
    int chunk = blockIdx.x & 7;
    int b0 = nodeblk * NBF;
    int c0 = chunk * FCW;
    int tid = threadIdx.x;

    // stage y slice: 8 nodes x 16 channels x 4 oo = 128 float4 (coalesced)
    if (tid < NBF * FCW) {
        int nn = tid >> 4;
        int ci = tid & 15;
        float4 v = *(const float4*)(g_y + (size_t)(b0 + nn) * 512 + (size_t)(c0 + ci) * 4);
        ysm[ci][0][nn] = v.x;
        ysm[ci][1][nn] = v.y;
        ysm[ci][2][nn] = v.z;
        ysm[ci][3][nn] = v.w;
    }
    __syncthreads();

    int f0 = tid * 2;
    int oo = f0 >> 7;            // 0..3, warp-uniform
    int n0 = f0 & 127;           // even
    int tsel = (oo > 0) ? 1 : 0;
    const float* wbase = w_lin + (size_t)tsel * CN * CN + (size_t)c0 * CN + n0;

    unsigned long long accA[4] = {0ull, 0ull, 0ull, 0ull};  // output n0,  node pairs
    unsigned long long accB[4] = {0ull, 0ull, 0ull, 0ull};  // output n0+1
#pragma unroll
    for (int ci = 0; ci < FCW; ci++) {
        float2 wv = *(const float2*)(wbase + ci * 128);
        unsigned long long w0p, w1p;
        asm("mov.b64 %0, {%1, %1};" : "=l"(w0p) : "f"(wv.x));
        asm("mov.b64 %0, {%1, %1};" : "=l"(w1p) : "f"(wv.y));
        ulonglong2 Y0 = *(const ulonglong2*)&ysm[ci][oo][0];  // nodes 0..3 packed (bcast)
        ulonglong2 Y1 = *(const ulonglong2*)&ysm[ci][oo][4];  // nodes 4..7 packed
        asm("fma.rn.f32x2 %0, %1, %2, %0;" : "+l"(accA[0]) : "l"(w0p), "l"(Y0.x));
        asm("fma.rn.f32x2 %0, %1, %2, %0;" : "+l"(accA[1]) : "l"(w0p), "l"(Y0.y));
        asm("fma.rn.f32x2 %0, %1, %2, %0;" : "+l"(accA[2]) : "l"(w0p), "l"(Y1.x));
        asm("fma.rn.f32x2 %0, %1, %2, %0;" : "+l"(accA[3]) : "l"(w0p), "l"(Y1.y));
        asm("fma.rn.f32x2 %0, %1, %2, %0;" : "+l"(accB[0]) : "l"(w1p), "l"(Y0.x));
        asm("fma.rn.f32x2 %0, %1, %2, %0;" : "+l"(accB[1]) : "l"(w1p), "l"(Y0.y));
        asm("fma.rn.f32x2 %0, %1, %2, %0;" : "+l"(accB[2]) : "l"(w1p), "l"(Y1.x));
        asm("fma.rn.f32x2 %0, %1, %2, %0;" : "+l"(accB[3]) : "l"(w1p), "l"(Y1.y));
    }

    int s0 = (oo == 0) ? n0 : (128 + n0 * 3 + (oo - 1));
    int s1 = (oo == 0) ? (n0 + 1) : (128 + (n0 + 1) * 3 + (oo - 1));
    float* pb = g_part + (size_t)chunk * (BN * 512);
#pragma unroll
    for (int p = 0; p < 4; p++) {
        float a0, a1, b0v, b1v;
        asm("mov.b64 {%0, %1}, %2;" : "=f"(a0), "=f"(a1) : "l"(accA[p]));
        asm("mov.b64 {%0, %1}, %2;" : "=f"(b0v), "=f"(b1v) : "l"(accB[p]));
        pb[(size_t)(b0 + 2 * p) * 512 + s0]     = a0;
        pb[(size_t)(b0 + 2 * p + 1) * 512 + s0] = a1;
        pb[(size_t)(b0 + 2 * p) * 512 + s1]     = b0v;
        pb[(size_t)(b0 + 2 * p + 1) * 512 + s1] = b1v;
    }
}

// ---------------- kernel 4b: reduce 8 partials + scale ----------------
__global__ void final_reduce(float* __restrict__ out) {
    const int PLANE = BN * 512 / 4;     // float4s per plane = 131072
    int t = blockIdx.x * 256 + threadIdx.x;
    const float4* p = (const float4*)g_part;
    float4 r = p[t];
#pragma unroll
    for (int q = 1; q < FCH; q++) {
        float4 v = p[t + q * PLANE];
        r.x += v.x; r.y += v.y; r.z += v.z; r.w += v.w;
    }
    const float scale = 0.08838834764831845f; // 1/sqrt(128)
    r.x *= scale; r.y *= scale; r.z *= scale; r.w *= scale;
    ((float4*)out)[t] = r;
}

// ---------------- launch ----------------
extern "C" void kernel_launch(void* const* d_in, const int* in_sizes, int n_in,
                              void* d_out, int out_size) {
    const float* x    = (const float*)d_in[0];
    const float* u3_0 = (const float*)d_in[1];
    const float* u3_1 = (const float*)d_in[2];
    const float* u2_0 = (const float*)d_in[3];
    const float* u2_1 = (const float*)d_in[4];
    const float* u1_0 = (const float*)d_in[5];
    const float* u1_1 = (const float*)d_in[6];
    const float* w3   = (const float*)d_in[7];
    const float* w2   = (const float*)d_in[8];
    const float* w1   = (const float*)d_in[9];
    const float* wlin = (const float*)d_in[10];
    const int*   sp   = (const int*)d_in[11];

    bucket_kernel<<<1, BN>>>(sp);
    sbuild_kernel<<<SN * NSLOTS, 128>>>(u3_0, u3_1, u2_0, u2_1, u1_0, u1_1, w3, w2, w1);
    main_kernel<<<128 * 8, 128>>>(x);       // 8 = max 256-node chunks over species
    final_part<<<128 * FCH, 256>>>(wlin);
    final_reduce<<<BN * 512 / 4 / 256, 256>>>((float*)d_out);
}

// round 12
// speedup vs baseline: 1.1749x; 1.1749x over previous
#include <cuda_runtime.h>

#define BN 1024
#define CN 128
#define DN 16
#define SN 4
#define K3N 23
#define K2N 5
#define K1N 2
#define ON 4

// Stream layout per (e,c), consumed in exactly this order:
//   for i in 0..15:  [S1: 4 floats]
//     for j in i..15:  [S2: 4 floats]
//       for h in (j>>1)..7:  [8 floats: (o0l0,o0l1,o1l0,o1l1,o2l0,o2l1,o3l0,o3l1)]
// total floats = 16*4 + 136*4 + 444*8 = 4160
#define STREAMF 4160
#define NSLOTS  596   // 16 S1 + 136 S2 + 444 h-slots

#define FCH 4         // final channel chunks
#define FCW 32        // channels per chunk
#define NBF 4         // nodes per final_part block

// ---------------- static device scratch ----------------
__device__ float g_stream[(size_t)SN * CN * STREAMF];   // 8.5 MB
__device__ float g_y[(size_t)BN * CN * ON];
__device__ float g_part[(size_t)FCH * BN * 512];        // 8.4 MB partials
__device__ int   g_bucket[SN * BN];
__device__ int   g_cnt[SN];
__device__ int   g_sched[16];
__device__ int   g_nsched;

// ---------------- symmetrized-u helpers ----------------
__device__ __forceinline__ float u3val(int o, int i, int j, int l, int k,
                                       const float* __restrict__ u3_0,
                                       const float* __restrict__ u3_1) {
    return (o == 0) ? u3_0[((i * 16 + j) * 16 + l) * K3N + k]
                    : u3_1[((((o - 1) * 16 + i) * 16 + j) * 16 + l) * K3N + k];
}
// orbit sum over distinct permutations of sorted triple a<=b<=g
__device__ __forceinline__ float orbit3(int o, int a, int b, int g, int k,
                                        const float* __restrict__ A,
                                        const float* __restrict__ B) {
    if (a == b && b == g) return u3val(o, a, a, a, k, A, B);
    if (a == b) return u3val(o, a, a, g, k, A, B) + u3val(o, a, g, a, k, A, B) + u3val(o, g, a, a, k, A, B);
    if (b == g) return u3val(o, a, b, b, k, A, B) + u3val(o, b, a, b, k, A, B) + u3val(o, b, b, a, k, A, B);
    return u3val(o, a, b, g, k, A, B) + u3val(o, a, g, b, k, A, B) + u3val(o, b, a, g, k, A, B)
         + u3val(o, b, g, a, k, A, B) + u3val(o, g, a, b, k, A, B) + u3val(o, g, b, a, k, A, B);
}
__device__ __forceinline__ float u2val(int o, int i, int j, int k,
                                       const float* __restrict__ u2_0,
                                       const float* __restrict__ u2_1) {
    return (o == 0) ? u2_0[(i * 16 + j) * K2N + k]
                    : u2_1[(((o - 1) * 16 + i) * 16 + j) * K2N + k];
}

// ---------------- kernel 1: build coefficient stream (+ bucket in block 0) ----------------
// grid = 4 species * 596 slots; 128 threads = channel c.
__global__ void sbuild_kernel(const float* __restrict__ u3_0, const float* __restrict__ u3_1,
                              const float* __restrict__ u2_0, const float* __restrict__ u2_1,
                              const float* __restrict__ u1_0, const float* __restrict__ u1_1,
                              const float* __restrict__ w3,   const float* __restrict__ w2,
                              const float* __restrict__ w1,   const int* __restrict__ sp) {
    __shared__ int scnt[SN];

    // block 0 additionally buckets nodes by species + builds 128-node chunk schedule
    if (blockIdx.x == 0) {
        int t = threadIdx.x;
        if (t < SN) scnt[t] = 0;
        __syncthreads();
#pragma unroll
        for (int m = 0; m < BN / 128; m++) {
            int node = t + m * 128;
            int e2 = sp[node];
            int pos = atomicAdd(&scnt[e2], 1);
            g_bucket[e2 * BN + pos] = node;
        }
        __syncthreads();
        if (t < SN) g_cnt[t] = scnt[t];
        if (t == 0) {
            int n = 0;
            for (int e2 = 0; e2 < SN; e2++)
                for (int s2 = 0; s2 < scnt[e2]; s2 += 128)
                    g_sched[n++] = (e2 << 16) | s2;
            g_nsched = n;
        }
    }

    int e = blockIdx.x / NSLOTS;
    int slot = blockIdx.x % NSLOTS;
    int c = threadIdx.x;

    // locate this slot in the canonical stream order (thread 0 only, broadcast)
    __shared__ int sinfo[5];
    if (threadIdx.x == 0) {
        int s = slot, type = -1, I = 0, J = 0, H = 0, mypos = 0, pos = 0;
        for (int i = 0; i < 16 && type < 0; i++) {
            if (s == 0) { type = 0; I = i; mypos = pos; break; }
            s--; pos += 4;
            for (int j = i; j < 16; j++) {
                if (s == 0) { type = 1; I = i; J = j; mypos = pos; break; }
                s--; pos += 4;
                int nh = 8 - (j >> 1);
                if (s < nh) { type = 2; I = i; J = j; H = (j >> 1) + s; mypos = pos + s * 8; break; }
                s -= nh; pos += nh * 8;
            }
        }
        sinfo[0] = type; sinfo[1] = I; sinfo[2] = J; sinfo[3] = H; sinfo[4] = mypos;
    }
    __syncthreads();
    int type = sinfo[0], I = sinfo[1], J = sinfo[2], H = sinfo[3], mypos = sinfo[4];
    size_t base = (size_t)(e * CN + c) * STREAMF + mypos;

    if (type == 0) {            // S1: uw1[o,I]
#pragma unroll
        for (int o = 0; o < 4; o++) {
            int tt = (o > 0);
            float acc = 0.f;
#pragma unroll
            for (int k = 0; k < K1N; k++) {
                float uu = (o == 0) ? u1_0[I * K1N + k] : u1_1[((o - 1) * 16 + I) * K1N + k];
                acc = fmaf(uu, w1[((tt * SN + e) * K1N + k) * CN + c], acc);
            }
            g_stream[base + o] = acc;
        }
    } else if (type == 1) {     // S2: orbit-symmetrized uw2 for pair (I<=J)
#pragma unroll
        for (int o = 0; o < 4; o++) {
            int tt = (o > 0);
            float acc = 0.f;
#pragma unroll
            for (int k = 0; k < K2N; k++) {
                float uu = u2val(o, I, J, k, u2_0, u2_1);
                if (I < J) uu += u2val(o, J, I, k, u2_0, u2_1);
                acc = fmaf(uu, w2[((tt * SN + e) * K2N + k) * CN + c], acc);
            }
            g_stream[base + o] = acc;
        }
    } else {                    // h-slot: 8 values (4 o x 2 l), orbit-symmetrized uw3
        __shared__ float us[K3N][8];
        for (int v = threadIdx.x; v < K3N * 8; v += 128) {
            int k = v >> 3, q = v & 7;
            int o = q >> 1, dl = q & 1, l = 2 * H + dl;
            float val = 0.f;
            if (l >= J) val = orbit3(o, I, J, l, k, u3_0, u3_1);
            us[k][q] = val;
        }
        __syncthreads();
        float w3r0[K3N], w3r1[K3N];
#pragma unroll
        for (int k = 0; k < K3N; k++) {
            w3r0[k] = w3[((0 * SN + e) * K3N + k) * CN + c];
            w3r1[k] = w3[((1 * SN + e) * K3N + k) * CN + c];
        }
        float acc[8] = {0, 0, 0, 0, 0, 0, 0, 0};
#pragma unroll
        for (int k = 0; k < K3N; k++) {
            float4 a = *(const float4*)&us[k][0];
            float4 b = *(const float4*)&us[k][4];
            acc[0] = fmaf(a.x, w3r0[k], acc[0]);
            acc[1] = fmaf(a.y, w3r0[k], acc[1]);
            acc[2] = fmaf(a.z, w3r1[k], acc[2]);
            acc[3] = fmaf(a.w, w3r1[k], acc[3]);
            acc[4] = fmaf(b.x, w3r1[k], acc[4]);
            acc[5] = fmaf(b.y, w3r1[k], acc[5]);
            acc[6] = fmaf(b.z, w3r1[k], acc[6]);
            acc[7] = fmaf(b.w, w3r1[k], acc[7]);
        }
#pragma unroll
        for (int q = 0; q < 8; q++) g_stream[base + q] = acc[q];
    }
}

// ---------------- kernel 2: main contraction (R9 form: 1 node/thread) ----------------
// One thread per (node, channel). Block = (c, 128-node chunk of one species).
__global__ void __launch_bounds__(128, 4) main_kernel(const float* __restrict__ x) {
    __shared__ float4 st4[STREAMF / 4];
    int bx = blockIdx.x;
    int c = bx & 127;
    int chunk = bx >> 7;
    if (chunk >= g_nsched) return;
    int si = g_sched[chunk];
    int e = si >> 16, start = si & 0xffff;

    // stage this (e,c) coefficient stream into smem (coalesced)
    const float4* src = (const float4*)(g_stream + (size_t)(e * CN + c) * STREAMF);
    for (int p = threadIdx.x; p < STREAMF / 4; p += 128) st4[p] = src[p];

    int cnt = g_cnt[e];
    int idx = start + threadIdx.x;
    bool active = idx < cnt;
    int b = active ? g_bucket[e * BN + idx] : 0;

    float xv[16];
    {
        float4 z = make_float4(0.f, 0.f, 0.f, 0.f);
        float4 xr[4] = {z, z, z, z};
        if (active) {
            const float4* xp = (const float4*)(x + ((size_t)b * CN + c) * 16);
            xr[0] = xp[0]; xr[1] = xp[1]; xr[2] = xp[2]; xr[3] = xp[3];
        }
        *(float4*)&xv[0]  = xr[0];
        *(float4*)&xv[4]  = xr[1];
        *(float4*)&xv[8]  = xr[2];
        *(float4*)&xv[12] = xr[3];
    }
    unsigned long long Xp[8];
#pragma unroll
    for (int h = 0; h < 8; h++)
        asm("mov.b64 %0, {%1, %2};" : "=l"(Xp[h]) : "f"(xv[2 * h]), "f"(xv[2 * h + 1]));

    __syncthreads();
    const float* sp = (const float*)st4;

    unsigned long long acc3[4] = {0ull, 0ull, 0ull, 0ull};  // packed (even-l, odd-l) sums per o
    float accs[4] = {0.f, 0.f, 0.f, 0.f};

#pragma unroll
    for (int i = 0; i < 16; i++) {
        float4 s1 = *(const float4*)sp; sp += 4;
        accs[0] = fmaf(s1.x, xv[i], accs[0]);
        accs[1] = fmaf(s1.y, xv[i], accs[1]);
        accs[2] = fmaf(s1.z, xv[i], accs[2]);
        accs[3] = fmaf(s1.w, xv[i], accs[3]);
#pragma unroll
        for (int j = i; j < 16; j++) {
            float p = xv[i] * xv[j];
            float4 s2 = *(const float4*)sp; sp += 4;
            accs[0] = fmaf(s2.x, p, accs[0]);
            accs[1] = fmaf(s2.y, p, accs[1]);
            accs[2] = fmaf(s2.z, p, accs[2]);
            accs[3] = fmaf(s2.w, p, accs[3]);
            unsigned long long p2;
            asm("mov.b64 %0, {%1, %1};" : "=l"(p2) : "f"(p));
#pragma unroll
            for (int h = (j >> 1); h < 8; h++) {
                unsigned long long m2;
                asm("mul.rn.f32x2 %0, %1, %2;" : "=l"(m2) : "l"(p2), "l"(Xp[h]));
                ulonglong2 qa = *(const ulonglong2*)sp;
                ulonglong2 qb = *(const ulonglong2*)(sp + 4);
                sp += 8;
                asm("fma.rn.f32x2 %0, %1, %2, %0;" : "+l"(acc3[0]) : "l"(qa.x), "l"(m2));
                asm("fma.rn.f32x2 %0, %1, %2, %0;" : "+l"(acc3[1]) : "l"(qa.y), "l"(m2));
                asm("fma.rn.f32x2 %0, %1, %2, %0;" : "+l"(acc3[2]) : "l"(qb.x), "l"(m2));
                asm("fma.rn.f32x2 %0, %1, %2, %0;" : "+l"(acc3[3]) : "l"(qb.y), "l"(m2));
            }
        }
    }

    if (active) {
        float out[4];
#pragma unroll
        for (int o = 0; o < 4; o++) {
            float lo, hi;
            asm("mov.b64 {%0, %1}, %2;" : "=f"(lo), "=f"(hi) : "l"(acc3[o]));
            out[o] = accs[o] + lo + hi;
        }
        *(float4*)(g_y + ((size_t)b * CN + c) * ON) = *(float4*)out;
    }
}

// ---------------- kernel 3a: equivariant linear, c-split partials ----------------
// grid = 1024 = (256 node-groups of 4 x 4 channel-chunks); block = 256 threads.
// Per-thread w MLP stays 32 (full 32-channel chunk, fully unrolled LDG.64s);
// 2x blocks vs R9 -> ~14 warps/SMSP of latency hiding.
__global__ void __launch_bounds__(256) final_part(const float* __restrict__ w_lin) {
    __shared__ float ysm[FCW][4][NBF];   // [ci][oo][nn], 2 KB
    int nodeblk = blockIdx.x >> 2;
    int chunk = blockIdx.x & 3;
    int b0 = nodeblk * NBF;
    int c0 = chunk * FCW;
    int tid = threadIdx.x;

    // stage y slice: 4 nodes x 32 channels x 4 oo = 128 float4 (coalesced)
    if (tid < NBF * FCW) {
        int nn = tid >> 5;
        int ci = tid & 31;
        float4 v = *(const float4*)(g_y + (size_t)(b0 + nn) * 512 + (size_t)(c0 + ci) * 4);
        ysm[ci][0][nn] = v.x;
        ysm[ci][1][nn] = v.y;
        ysm[ci][2][nn] = v.z;
        ysm[ci][3][nn] = v.w;
    }
    __syncthreads();

    int f0 = tid * 2;
    int oo = f0 >> 7;            // 0..3, warp-uniform
    int n0 = f0 & 127;           // even
    int tsel = (oo > 0) ? 1 : 0;
    const float* wbase = w_lin + (size_t)tsel * CN * CN + (size_t)c0 * CN + n0;

    unsigned long long accA[2] = {0ull, 0ull};  // output n0,  node pairs (0,1),(2,3)
    unsigned long long accB[2] = {0ull, 0ull};  // output n0+1
#pragma unroll
    for (int ci = 0; ci < FCW; ci++) {
        float2 wv = *(const float2*)(wbase + ci * 128);
        unsigned long long w0p, w1p;
        asm("mov.b64 %0, {%1, %1};" : "=l"(w0p) : "f"(wv.x));
        asm("mov.b64 %0, {%1, %1};" : "=l"(w1p) : "f"(wv.y));
        ulonglong2 Y0 = *(const ulonglong2*)&ysm[ci][oo][0];  // nodes 0..3 packed (bcast)
        asm("fma.rn.f32x2 %0, %1, %2, %0;" : "+l"(accA[0]) : "l"(w0p), "l"(Y0.x));
        asm("fma.rn.f32x2 %0, %1, %2, %0;" : "+l"(accA[1]) : "l"(w0p), "l"(Y0.y));
        asm("fma.rn.f32x2 %0, %1, %2, %0;" : "+l"(accB[0]) : "l"(w1p), "l"(Y0.x));
        asm("fma.rn.f32x2 %0, %1, %2, %0;" : "+l"(accB[1]) : "l"(w1p), "l"(Y0.y));
    }

    int s0 = (oo == 0) ? n0 : (128 + n0 * 3 + (oo - 1));
    int s1 = (oo == 0) ? (n0 + 1) : (128 + (n0 + 1) * 3 + (oo - 1));
    float* pb = g_part + (size_t)chunk * (BN * 512);
#pragma unroll
    for (int p = 0; p < 2; p++) {
        float a0, a1, b0v, b1v;
        asm("mov.b64 {%0, %1}, %2;" : "=f"(a0), "=f"(a1) : "l"(accA[p]));
        asm("mov.b64 {%0, %1}, %2;" : "=f"(b0v), "=f"(b1v) : "l"(accB[p]));
        pb[(size_t)(b0 + 2 * p) * 512 + s0]     = a0;
        pb[(size_t)(b0 + 2 * p + 1) * 512 + s0] = a1;
        pb[(size_t)(b0 + 2 * p) * 512 + s1]     = b0v;
        pb[(size_t)(b0 + 2 * p + 1) * 512 + s1] = b1v;
    }
}

// ---------------- kernel 3b: reduce 4 partials + scale ----------------
__global__ void final_reduce(float* __restrict__ out) {
    const int PLANE = BN * 512 / 4;     // float4s per plane = 131072
    int t = blockIdx.x * 256 + threadIdx.x;
    const float4* p = (const float4*)g_part;
    float4 a = p[t], b = p[t + PLANE], c = p[t + 2 * PLANE], d = p[t + 3 * PLANE];
    const float scale = 0.08838834764831845f; // 1/sqrt(128)
    float4 r;
    r.x = (a.x + b.x + c.x + d.x) * scale;
    r.y = (a.y + b.y + c.y + d.y) * scale;
    r.z = (a.z + b.z + c.z + d.z) * scale;
    r.w = (a.w + b.w + c.w + d.w) * scale;
    ((float4*)out)[t] = r;
}

// ---------------- launch ----------------
extern "C" void kernel_launch(void* const* d_in, const int* in_sizes, int n_in,
                              void* d_out, int out_size) {
    const float* x    = (const float*)d_in[0];
    const float* u3_0 = (const float*)d_in[1];
    const float* u3_1 = (const float*)d_in[2];
    const float* u2_0 = (const float*)d_in[3];
    const float* u2_1 = (const float*)d_in[4];
    const float* u1_0 = (const float*)d_in[5];
    const float* u1_1 = (const float*)d_in[6];
    const float* w3   = (const float*)d_in[7];
    const float* w2   = (const float*)d_in[8];
    const float* w1   = (const float*)d_in[9];
    const float* wlin = (const float*)d_in[10];
    const int*   sp   = (const int*)d_in[11];

    sbuild_kernel<<<SN * NSLOTS, 128>>>(u3_0, u3_1, u2_0, u2_1, u1_0, u1_1, w3, w2, w1, sp);
    main_kernel<<<128 * 11, 128>>>(x);      // 11 = hard bound on 128-node chunks
    final_part<<<(BN / NBF) * FCH, 256>>>(wlin);
    final_reduce<<<BN * 512 / 4 / 256, 256>>>((float*)d_out);
}